// round 7
// baseline (speedup 1.0000x reference)
#include <cuda_runtime.h>
#include <math_constants.h>

#define B_     4
#define C_     256
#define H_     64
#define W_     64
#define NROI   128
#define OUTK   7
#define STRIDE 65   // smem row stride in floats: bank = (y+x) & 31

// One block per (b, c) plane. Stage the plane in smem, pool all rois of batch b
// from smem. Bin bounds: exact integer math (bit-identical to reference f32,
// verified rel_err == 0 in rounds 4-6).
__global__ __launch_bounds__(256) void roi_pool_plane(
    const float* __restrict__ feat,
    const int*   __restrict__ rois,
    float*       __restrict__ out)
{
    __shared__ float plane[H_ * STRIDE];
    __shared__ int   s_idx[NROI], s_x1[NROI], s_y1[NROI], s_rw[NROI], s_rh[NROI];
    __shared__ int   s_cnt;

    const int tid = threadIdx.x;
    const int bc  = blockIdx.x;      // b*256 + c
    const int b   = bc >> 8;
    const int c   = bc & 255;

    if (tid == 0) s_cnt = 0;
    __syncthreads();

    // ---- phase 0: compact the rois belonging to batch b (parallel) ----
    if (tid < NROI) {
        const int rb = __ldg(rois + tid * 5);
        if (rb == b) {
            const int p = atomicAdd(&s_cnt, 1);
            const int x1 = __ldg(rois + tid * 5 + 1);
            const int y1 = __ldg(rois + tid * 5 + 2);
            const int x2 = __ldg(rois + tid * 5 + 3);
            const int y2 = __ldg(rois + tid * 5 + 4);
            s_idx[p] = tid;
            s_x1[p]  = x1;
            s_y1[p]  = y1;
            s_rw[p]  = x2 - x1 + 1;
            s_rh[p]  = y2 - y1 + 1;
        }
    }

    // ---- phase 1: stage the 64x64 plane into smem (1024 float4, 4/thread) ----
    const float4* src = (const float4*)(feat + (size_t)bc * (H_ * W_));
    #pragma unroll
    for (int k = 0; k < 4; ++k) {
        const int g = k * 256 + tid;          // float4 index in plane
        const float4 v = __ldg(src + g);
        const int y = g >> 4;                 // 16 float4 per row
        const int x = (g & 15) << 2;
        float* p = &plane[y * STRIDE + x];
        p[0] = v.x; p[1] = v.y; p[2] = v.z; p[3] = v.w;
    }
    __syncthreads();

    // ---- phase 2: flattened (roi, bin) work, strided over 256 threads ----
    const int cnt   = s_cnt;
    const int total = cnt * (OUTK * OUTK);
    for (int u = tid; u < total; u += 256) {
        const int k   = u / 49;
        const int bin = u - k * 49;
        const int i   = bin / OUTK;
        const int j   = bin - i * OUTK;

        const int rh = s_rh[k], rw = s_rw[k];
        const int hs = (i * rh) / 7, he = ((i + 1) * rh) / 7;
        const int ws = (j * rw) / 7, we = ((j + 1) * rw) / 7;
        const int nx = we - ws;
        const bool valid = (he > hs) && (nx > 0);

        const float* row = &plane[(s_y1[k] + hs) * STRIDE + s_x1[k] + ws];
        float m0 = -CUDART_INF_F, m1 = -CUDART_INF_F;
        for (int y = hs; y < he; ++y) {
            int xx = 0;
            for (; xx + 2 <= nx; xx += 2) {
                m0 = fmaxf(m0, row[xx]);
                m1 = fmaxf(m1, row[xx + 1]);
            }
            if (xx < nx) m0 = fmaxf(m0, row[xx]);
            row += STRIDE;
        }
        const float m = fmaxf(m0, m1);

        out[((size_t)s_idx[k] * C_ + c) * (OUTK * OUTK) + bin] = valid ? m : 0.0f;
    }
}

extern "C" void kernel_launch(void* const* d_in, const int* in_sizes, int n_in,
                              void* d_out, int out_size) {
    const float* features = (const float*)d_in[0];
    const int*   rois     = (const int*)d_in[1];
    float*       out      = (float*)d_out;

    roi_pool_plane<<<B_ * C_, 256>>>(features, rois, out);
}

// round 8
// speedup vs baseline: 1.2578x; 1.2578x over previous
#include <cuda_runtime.h>
#include <math_constants.h>

#define B_     4
#define C_     256
#define H_     64
#define W_     64
#define NROI   128
#define OUTK   7
#define STRIDE 65              // smem row stride: bank = (y+x) & 31
#define PLANE  (H_ * STRIDE)   // floats per staged plane

// One block per (b, channel-pair). Stage BOTH channel planes in smem, pool all
// rois of batch b from smem; every (roi,bin) task drives two channels at once.
// Bin bounds: exact integer math, proven bit-identical to the reference's f32
// bounds (rel_err == 0 in rounds 4-7); precomputed per roi in phase 0.
__global__ __launch_bounds__(256) void roi_pool_plane2(
    const float* __restrict__ feat,
    const int*   __restrict__ rois,
    float*       __restrict__ out)
{
    __shared__ float plane[2 * PLANE];
    __shared__ int   s_idx[NROI], s_x1[NROI], s_y1[NROI];
    __shared__ unsigned char s_hb[NROI][8], s_wb[NROI][8];
    __shared__ int   s_cnt;

    const int tid = threadIdx.x;
    const int blk = blockIdx.x;          // b*(C/2) + cpair
    const int b   = blk >> 7;
    const int c0  = (blk & 127) << 1;    // channels c0, c0+1

    if (tid == 0) s_cnt = 0;
    __syncthreads();

    // ---- phase 0: compact rois of batch b + precompute bin boundaries ----
    if (tid < NROI) {
        const int rb = __ldg(rois + tid * 5);
        if (rb == b) {
            const int p  = atomicAdd(&s_cnt, 1);
            const int x1 = __ldg(rois + tid * 5 + 1);
            const int y1 = __ldg(rois + tid * 5 + 2);
            const int x2 = __ldg(rois + tid * 5 + 3);
            const int y2 = __ldg(rois + tid * 5 + 4);
            const int rh = y2 - y1 + 1;  // 5..48
            const int rw = x2 - x1 + 1;  // 5..48
            s_idx[p] = tid;
            s_x1[p]  = x1;
            s_y1[p]  = y1;
            #pragma unroll
            for (int i = 0; i < 8; ++i) {
                s_hb[p][i] = (unsigned char)((i * rh) / 7);
                s_wb[p][i] = (unsigned char)((i * rw) / 7);
            }
        }
    }

    // ---- phase 1: stage the two 64x64 planes (2048 float4, 8/thread) ----
    const float4* src = (const float4*)(feat + ((size_t)b * C_ + c0) * (H_ * W_));
    #pragma unroll
    for (int k = 0; k < 8; ++k) {
        const int g  = k * 256 + tid;         // float4 index over both planes
        const int pl = g >> 10;               // 1024 float4 per plane
        const int gi = g & 1023;
        const float4 v = __ldg(src + g);
        const int y = gi >> 4;                // 16 float4 per row
        const int x = (gi & 15) << 2;
        float* p = &plane[pl * PLANE + y * STRIDE + x];
        p[0] = v.x; p[1] = v.y; p[2] = v.z; p[3] = v.w;
    }
    __syncthreads();

    // ---- phase 2: flattened (roi, bin) tasks, two channels per task ----
    const int cnt   = s_cnt;
    const int total = cnt * (OUTK * OUTK);
    for (int u = tid; u < total; u += 256) {
        const int k   = u / 49;
        const int bin = u - k * 49;
        const int i   = bin / OUTK;
        const int j   = bin - i * OUTK;

        const int hs = s_hb[k][i], he = s_hb[k][i + 1];
        const int ws = s_wb[k][j], we = s_wb[k][j + 1];
        const int nx = we - ws;
        const bool valid = (he > hs) && (nx > 0);

        const float* r0 = &plane[(s_y1[k] + hs) * STRIDE + s_x1[k] + ws];
        const float* r1 = r0 + PLANE;

        float a0 = -CUDART_INF_F, a1 = -CUDART_INF_F;   // channel c0
        float b0 = -CUDART_INF_F, b1 = -CUDART_INF_F;   // channel c0+1
        for (int y = hs; y < he; ++y) {
            int xx = 0;
            for (; xx + 2 <= nx; xx += 2) {
                a0 = fmaxf(a0, r0[xx]);     b0 = fmaxf(b0, r1[xx]);
                a1 = fmaxf(a1, r0[xx + 1]); b1 = fmaxf(b1, r1[xx + 1]);
            }
            if (xx < nx) { a0 = fmaxf(a0, r0[xx]); b0 = fmaxf(b0, r1[xx]); }
            r0 += STRIDE; r1 += STRIDE;
        }
        const float m0 = fmaxf(a0, a1);
        const float m1 = fmaxf(b0, b1);

        const size_t obase = ((size_t)s_idx[k] * C_ + c0) * (OUTK * OUTK) + bin;
        out[obase]      = valid ? m0 : 0.0f;
        out[obase + 49] = valid ? m1 : 0.0f;
    }
}

extern "C" void kernel_launch(void* const* d_in, const int* in_sizes, int n_in,
                              void* d_out, int out_size) {
    const float* features = (const float*)d_in[0];
    const int*   rois     = (const int*)d_in[1];
    float*       out      = (float*)d_out;

    roi_pool_plane2<<<B_ * (C_ / 2), 256>>>(features, rois, out);
}